// round 8
// baseline (speedup 1.0000x reference)
#include <cuda_runtime.h>
#include <math.h>

// ---------------------------------------------------------------------------
// SOM sequential scan, round 8: R6 + tail-deadlock fix.
//
// 128 CTAs x 288 threads. Warps 0..7 each own ONE cell (cell = cta*8 + wid),
// 12 dims/lane, weights in registers. Warp 8 = comm-only (highest wid ->
// favored by the hi-wid-first intra-SMSP arbiter).
//
// Global argmin per step: 128 slots (one per CTA), double-buffered rows,
// slot = (d2_bits<<32) | (cell<<14) | (step+1 & 0x3FFF).
//
// BARRIER PROTOCOL (deadlock-free for ALL iterations):
//   bar1: comm arrives once per iter; workers bar.sync once per step.
//   bar2: workers arrive once per step (EVERY step) + once in prologue;
//         comm bar.sync once per iter (EVERY iter, incl. the last).
//   Invariant: comm's bar1 arrive at iter s is preceded by its bar2 wait,
//   which pairs with the workers' step s-1 arrival, which follows their
//   step s-1 bar1 wait -> comm can never double-arrive one bar1 phase.
//   (The missing last-iter bar2 wait in R3/R6/R7 allowed exactly that and
//   intermittently deadlocked the tail.)
//
// Comm warp, iter s:
//   issue 4 poll LDGs -> bar.sync(2) + LDS publish operands (overlapped
//   with poll RTT) -> finish poll -> redux-min pair (BMU) -> STS s_bmu
//   -> bar.arrive(1) [early worker release]
//   -> LUT + 2 FMA -> redux-min pair -> relaxed STG publish (tag s+2).
// Worker warps, step s:
//   prefetch x_{s+2} -> bar.sync(1) (sleep) -> read s_bmu -> update w +
//   next P/-2Q/R -> butterfly -> STS -> bar.arrive(2).
// ---------------------------------------------------------------------------

#define SOM_G    128
#define SOM_TPB  288
#define SOM_DIM  384
#define SOM_NS   8192
#define SOM_EPW  12
#define SOM_CPC  8
#define SOM_MAXE 2
#define TAGMASK  0x3FFFu
#define WID_COMM 8

__device__ unsigned long long g_slots[2][SOM_G];

static __device__ __forceinline__ unsigned long long ld_rlx(const unsigned long long* p) {
    unsigned long long v;
    asm volatile("ld.relaxed.gpu.global.b64 %0, [%1];" : "=l"(v) : "l"(p) : "memory");
    return v;
}
static __device__ __forceinline__ void st_rlx(unsigned long long* p, unsigned long long v) {
    asm volatile("st.relaxed.gpu.global.b64 [%0], %1;" :: "l"(p), "l"(v) : "memory");
}
static __device__ __forceinline__ void bar_arrive(int id) {
    asm volatile("bar.arrive %0, %1;" :: "r"(id), "r"(SOM_TPB) : "memory");
}
static __device__ __forceinline__ void bar_wait(int id) {
    asm volatile("bar.sync %0, %1;" :: "r"(id), "r"(SOM_TPB) : "memory");
}
static __device__ __forceinline__ unsigned long long umin64(unsigned long long a,
                                                            unsigned long long b) {
    return a < b ? a : b;
}
// warp-wide min of packed (d2<<32 | cell<<14 | tag); tags identical across lanes
static __device__ __forceinline__ unsigned long long warp_min64(unsigned long long v) {
    unsigned hi  = (unsigned)(v >> 32);
    unsigned mhi = __reduce_min_sync(0xffffffffu, hi);
    unsigned lo  = (hi == mhi) ? (unsigned)v : 0xffffffffu;
    unsigned mlo = __reduce_min_sync(0xffffffffu, lo);
    return ((unsigned long long)mhi << 32) | mlo;
}

static __device__ __forceinline__ int read_epochs(const int* p) {
    int e = p[0];
    if (e < 1 || e > SOM_MAXE) {
        float fe = __int_as_float(e);
        if (fe >= 1.0f && fe <= (float)SOM_MAXE) e = (int)fe;
        else e = 1;
    }
    return e;
}

__global__ void som_init_slots() {
    int i = threadIdx.x;
    if (i < 2 * SOM_G) ((unsigned long long*)g_slots)[i] = 0ull;
}

__global__ void __launch_bounds__(SOM_TPB, 1)
som_kernel(const float* __restrict__ X,   // [8192, 384]
           const float* __restrict__ W0,  // [32, 32, 384]
           const int* __restrict__ pep,
           float* __restrict__ out)       // [32, 32, 384]
{
    __shared__ float lut[63 * 64];               // 0.1*exp(-0.5*sqrt(dx^2+dy^2))
    __shared__ float s_P[SOM_CPC], s_Qm2[SOM_CPC], s_R[SOM_CPC];
    __shared__ unsigned s_bmu[2];

    const int tid  = threadIdx.x;
    const int wid  = tid >> 5;
    const int lane = tid & 31;
    const int cta  = blockIdx.x;
    const int S    = read_epochs(pep) * SOM_NS;

    for (int i = tid; i < 63 * 64; i += SOM_TPB) {
        float fx = (float)((i >> 6) - 31);
        float fy = (float)((i & 63) - 31);
        lut[i] = 0.1f * expf(-0.5f * sqrtf(fx * fx + fy * fy));
    }

    // ---------------- worker state + prologue ----------------
    float w[SOM_EPW], v[SOM_EPW], xn[SOM_EPW];
    int cell = 0, cgx = 0, cgy = 0;
    if (wid < WID_COMM) {
        cell = cta * SOM_CPC + wid;
        cgx = cell >> 5; cgy = cell & 31;
        const float* wr = W0 + (size_t)cell * SOM_DIM + lane;
#pragma unroll
        for (int k = 0; k < SOM_EPW; k++) w[k] = wr[k * 32];
        const float* x0 = X + lane;
        const float* x1 = X + (size_t)SOM_DIM + lane;
        float p = 0.f, q = 0.f, r = 0.f;
#pragma unroll
        for (int k = 0; k < SOM_EPW; k++) {
            float a0 = x0[k * 32];
            float a1 = x1[k * 32];
            float vv = a0 - w[k];
            float uu = a1 - w[k];
            v[k]  = vv;
            xn[k] = a1;
            r = fmaf(vv, vv, r);
            q = fmaf(uu, vv, q);
            p = fmaf(uu, uu, p);
        }
#pragma unroll
        for (int o = 16; o; o >>= 1) {
            p += __shfl_xor_sync(0xffffffffu, p, o);
            q += __shfl_xor_sync(0xffffffffu, q, o);
            r += __shfl_xor_sync(0xffffffffu, r, o);
        }
        if (lane == 0) {
            s_P[wid]   = p;
            s_Qm2[wid] = -2.0f * q;
            s_R[wid]   = r;
        }
    }
    __syncthreads();

    if (wid == WID_COMM) {
        // ================= COMM WARP (highest wid) =================
        // publish step-0 mins (d2_0 == R), slot tag 1, row 0
        {
            unsigned long long pk = 0xFFFFFFFFFFFFFFFFull;
            if (lane < SOM_CPC) {
                unsigned pcell = (unsigned)(cta * SOM_CPC + lane);
                pk = ((unsigned long long)__float_as_uint(s_R[lane]) << 32)
                   | (pcell << 14) | 1u;
            }
            unsigned long long m = warp_min64(pk);
            if (lane == 0) st_rlx(&g_slots[0][cta], m);
        }

        const unsigned pc = (unsigned)(cta * SOM_CPC + (lane & 7));
        const int pgx = (int)(pc >> 5), pgy = (int)(pc & 31);

        for (int s = 0; s < S; s++) {
            const bool more = (s + 1 < S);

            // 1) issue the 4 poll LDGs FIRST — their L2 round-trip overlaps
            //    the bar2 wait below.
            const unsigned tag = (unsigned)(s + 1) & TAGMASK;
            const unsigned long long* base = &g_slots[s & 1][0];
            const unsigned long long *q0 = base + lane,      *q1 = base + lane + 32,
                                     *q2 = base + lane + 64, *q3 = base + lane + 96;
            unsigned long long v0 = ld_rlx(q0), v1 = ld_rlx(q1),
                               v2 = ld_rlx(q2), v3 = ld_rlx(q3);

            // 2) bar2 wait EVERY iteration (deadlock fix: gates our next
            //    bar1 arrive on workers having passed the previous bar1).
            bar_wait(2);
            float Pp = 0.f, Qp = 0.f, Rp = 0.f;
            if (lane < SOM_CPC) {
                Pp = s_P[lane]; Qp = s_Qm2[lane]; Rp = s_R[lane];
            }

            // 3) finish poll for step s
            for (;;) {
                bool b0 = ((unsigned)v0 & TAGMASK) != tag;
                bool b1 = ((unsigned)v1 & TAGMASK) != tag;
                bool b2 = ((unsigned)v2 & TAGMASK) != tag;
                bool b3 = ((unsigned)v3 & TAGMASK) != tag;
                if (!(b0 | b1 | b2 | b3)) break;
                if (b0) v0 = ld_rlx(q0);
                if (b1) v1 = ld_rlx(q1);
                if (b2) v2 = ld_rlx(q2);
                if (b3) v3 = ld_rlx(q3);
            }
            __syncwarp();
            unsigned long long gm =
                warp_min64(umin64(umin64(v0, v1), umin64(v2, v3)));
            const unsigned bcell = ((unsigned)gm >> 14) & 0x3FFu;
            if (lane == 0) s_bmu[s & 1] = bcell;

            // 4) early worker release
            bar_arrive(1);

            // 5) publish step s+1 (workers already running their pass)
            if (more) {
                unsigned long long pk = 0xFFFFFFFFFFFFFFFFull;
                if (lane < SOM_CPC) {
                    float a = lut[(pgx - (int)(bcell >> 5) + 31) * 64 +
                                  (pgy - (int)(bcell & 31) + 31)];
                    float d2 = fmaxf(fmaf(a, fmaf(a, Rp, Qp), Pp), 0.0f);
                    pk = ((unsigned long long)__float_as_uint(d2) << 32)
                       | (pc << 14) | ((unsigned)(s + 2) & TAGMASK);
                }
                unsigned long long pm = warp_min64(pk);
                if (lane == 0) st_rlx(&g_slots[(s + 1) & 1][cta], pm);
            }
        }
    } else {
        // ================= WORKER WARPS (wid 0..7) =================
        bar_arrive(2);  // prologue P/Q/R already in smem

        for (int s = 0; s < S; s++) {
            // prefetch x_{s+2} while waiting for BMU(s)
            float xf[SOM_EPW];
            {
                const float* xr =
                    X + (size_t)((s + 2) & (SOM_NS - 1)) * SOM_DIM + lane;
#pragma unroll
                for (int k = 0; k < SOM_EPW; k++) xf[k] = xr[k * 32];
            }
            bar_wait(1);  // sleep until BMU(s) ready
            const unsigned bcell = s_bmu[s & 1];
            const float a = lut[(cgx - (int)(bcell >> 5) + 31) * 64 +
                                (cgy - (int)(bcell & 31) + 31)];

            float p = 0.f, q = 0.f, r = 0.f;
#pragma unroll
            for (int k = 0; k < SOM_EPW; k++) {
                float wn = fmaf(a, v[k], w[k]);   // w^(s+1)
                float u  = xn[k] - wn;            // next v
                float z  = xf[k] - wn;
                r = fmaf(u, u, r);
                q = fmaf(z, u, q);
                p = fmaf(z, z, p);
                w[k]  = wn;
                v[k]  = u;
                xn[k] = xf[k];
            }
            // reduce + publish EVERY step (part of the deadlock fix)
#pragma unroll
            for (int o = 16; o; o >>= 1) {
                p += __shfl_xor_sync(0xffffffffu, p, o);
                q += __shfl_xor_sync(0xffffffffu, q, o);
                r += __shfl_xor_sync(0xffffffffu, r, o);
            }
            if (lane == 0) {
                s_P[wid]   = p;
                s_Qm2[wid] = -2.0f * q;
                s_R[wid]   = r;
            }
            bar_arrive(2);
        }

        // write final weights
        float* orow = out + (size_t)cell * SOM_DIM + lane;
#pragma unroll
        for (int k = 0; k < SOM_EPW; k++) orow[k * 32] = w[k];
    }
}

extern "C" void kernel_launch(void* const* d_in, const int* in_sizes, int n_in,
                              void* d_out, int out_size) {
    const float* X  = (const float*)d_in[0];
    const float* W0 = (const float*)d_in[1];
    const int* pep  = (const int*)d_in[3];
    (void)in_sizes; (void)n_in; (void)out_size;

    som_init_slots<<<1, 256>>>();
    som_kernel<<<SOM_G, SOM_TPB>>>(X, W0, pep, (float*)d_out);
}

// round 9
// speedup vs baseline: 1.3966x; 1.3966x over previous
#include <cuda_runtime.h>
#include <math.h>

// ---------------------------------------------------------------------------
// SOM sequential scan, round 9: UNGATED POLL warp-specialized pipeline.
//
// 128 CTAs x 288 threads. Workers wid 0..7 own one cell each (12 dims/lane,
// weights in registers). Comm = wid 8 (highest -> hi-wid-first arbiter
// priority while workers compute).
//
// Global argmin: 128 slots (one/CTA), double-buffered rows, word =
//   (d2_bits<<32) | (cell<<14) | (step+1 & 0x3FFF).
//
// Barrier protocol (named bars, counts all 288):
//   bar1: comm arrives once/iter; workers sync once/step (sleep for BMU).
//   bar2: workers arrive IMMEDIATELY BEFORE their bar1 wait ("parked");
//         comm waits before each bar1 arrive  -> release always safe.
//   bar3: workers arrive after STS of P/-2Q/R ("data ready") + prologue;
//         comm waits after discovery, before publish (satisfied long ago).
//   Double-arrive impossible: each party's re-arrive is transitively gated
//   through the other's consumption (verified for all three barriers).
//
// Comm iter s:  poll(s) [UNGATED] -> discovery -> STS s_bmu -> bar2 wait
//   -> bar1 arrive (release) -> [if more] bar3 wait -> LDS P/Qm2/R ->
//   LUT + 2 FMA -> redux-min pair -> relaxed STG publish (tag s+2).
// Worker step s: prefetch x_{s+2} -> bar2 arrive -> bar1 wait -> read bmu
//   -> update w + next P/-2Q/R -> butterfly -> STS -> bar3 arrive.
// Critical chain: discovery -> publish (~150) -> L2 (~250) -> remote spin
// (~150) ~= 600-700 cyc/step; worker pass (~500) fully hidden.
// ---------------------------------------------------------------------------

#define SOM_G    128
#define SOM_TPB  288
#define SOM_DIM  384
#define SOM_NS   8192
#define SOM_EPW  12
#define SOM_CPC  8
#define SOM_MAXE 2
#define TAGMASK  0x3FFFu
#define WID_COMM 8

__device__ unsigned long long g_slots[2][SOM_G];

static __device__ __forceinline__ unsigned long long ld_rlx(const unsigned long long* p) {
    unsigned long long v;
    asm volatile("ld.relaxed.gpu.global.b64 %0, [%1];" : "=l"(v) : "l"(p) : "memory");
    return v;
}
static __device__ __forceinline__ void st_rlx(unsigned long long* p, unsigned long long v) {
    asm volatile("st.relaxed.gpu.global.b64 [%0], %1;" :: "l"(p), "l"(v) : "memory");
}
static __device__ __forceinline__ void bar_arrive(int id) {
    asm volatile("bar.arrive %0, %1;" :: "r"(id), "r"(SOM_TPB) : "memory");
}
static __device__ __forceinline__ void bar_wait(int id) {
    asm volatile("bar.sync %0, %1;" :: "r"(id), "r"(SOM_TPB) : "memory");
}
static __device__ __forceinline__ unsigned long long umin64(unsigned long long a,
                                                            unsigned long long b) {
    return a < b ? a : b;
}
// warp-wide min of packed (d2<<32 | cell<<14 | tag); tags identical across lanes
static __device__ __forceinline__ unsigned long long warp_min64(unsigned long long v) {
    unsigned hi  = (unsigned)(v >> 32);
    unsigned mhi = __reduce_min_sync(0xffffffffu, hi);
    unsigned lo  = (hi == mhi) ? (unsigned)v : 0xffffffffu;
    unsigned mlo = __reduce_min_sync(0xffffffffu, lo);
    return ((unsigned long long)mhi << 32) | mlo;
}

static __device__ __forceinline__ int read_epochs(const int* p) {
    int e = p[0];
    if (e < 1 || e > SOM_MAXE) {
        float fe = __int_as_float(e);
        if (fe >= 1.0f && fe <= (float)SOM_MAXE) e = (int)fe;
        else e = 1;
    }
    return e;
}

__global__ void som_init_slots() {
    int i = threadIdx.x;
    if (i < 2 * SOM_G) ((unsigned long long*)g_slots)[i] = 0ull;
}

__global__ void __launch_bounds__(SOM_TPB, 1)
som_kernel(const float* __restrict__ X,   // [8192, 384]
           const float* __restrict__ W0,  // [32, 32, 384]
           const int* __restrict__ pep,
           float* __restrict__ out)       // [32, 32, 384]
{
    __shared__ float lut[63 * 64];               // 0.1*exp(-0.5*sqrt(dx^2+dy^2))
    __shared__ float s_P[SOM_CPC], s_Qm2[SOM_CPC], s_R[SOM_CPC];
    __shared__ unsigned s_bmu[2];

    const int tid  = threadIdx.x;
    const int wid  = tid >> 5;
    const int lane = tid & 31;
    const int cta  = blockIdx.x;
    const int S    = read_epochs(pep) * SOM_NS;

    for (int i = tid; i < 63 * 64; i += SOM_TPB) {
        float fx = (float)((i >> 6) - 31);
        float fy = (float)((i & 63) - 31);
        lut[i] = 0.1f * expf(-0.5f * sqrtf(fx * fx + fy * fy));
    }

    // ---------------- worker state + prologue ----------------
    float w[SOM_EPW], v[SOM_EPW], xn[SOM_EPW];
    int cell = 0, cgx = 0, cgy = 0;
    if (wid < WID_COMM) {
        cell = cta * SOM_CPC + wid;
        cgx = cell >> 5; cgy = cell & 31;
        const float* wr = W0 + (size_t)cell * SOM_DIM + lane;
#pragma unroll
        for (int k = 0; k < SOM_EPW; k++) w[k] = wr[k * 32];
        const float* x0 = X + lane;
        const float* x1 = X + (size_t)SOM_DIM + lane;
        float p = 0.f, q = 0.f, r = 0.f;
#pragma unroll
        for (int k = 0; k < SOM_EPW; k++) {
            float a0 = x0[k * 32];
            float a1 = x1[k * 32];
            float vv = a0 - w[k];
            float uu = a1 - w[k];
            v[k]  = vv;
            xn[k] = a1;
            r = fmaf(vv, vv, r);
            q = fmaf(uu, vv, q);
            p = fmaf(uu, uu, p);
        }
#pragma unroll
        for (int o = 16; o; o >>= 1) {
            p += __shfl_xor_sync(0xffffffffu, p, o);
            q += __shfl_xor_sync(0xffffffffu, q, o);
            r += __shfl_xor_sync(0xffffffffu, r, o);
        }
        if (lane == 0) {
            s_P[wid]   = p;
            s_Qm2[wid] = -2.0f * q;
            s_R[wid]   = r;
        }
    }
    __syncthreads();

    if (wid == WID_COMM) {
        // ================= COMM WARP (wid 8, highest) =================
        // publish step-0 mins (d2_0 == R), slot tag 1, row 0
        {
            unsigned long long pk = 0xFFFFFFFFFFFFFFFFull;
            if (lane < SOM_CPC) {
                unsigned pcell = (unsigned)(cta * SOM_CPC + lane);
                pk = ((unsigned long long)__float_as_uint(s_R[lane]) << 32)
                   | (pcell << 14) | 1u;
            }
            unsigned long long m = warp_min64(pk);
            if (lane == 0) st_rlx(&g_slots[0][cta], m);
        }

        const unsigned pc = (unsigned)(cta * SOM_CPC + (lane & 7));
        const int pgx = (int)(pc >> 5), pgy = (int)(pc & 31);

        for (int s = 0; s < S; s++) {
            const bool more = (s + 1 < S);

            // 1) UNGATED poll for step s
            const unsigned tag = (unsigned)(s + 1) & TAGMASK;
            const unsigned long long* base = &g_slots[s & 1][0];
            const unsigned long long *q0 = base + lane,      *q1 = base + lane + 32,
                                     *q2 = base + lane + 64, *q3 = base + lane + 96;
            unsigned long long v0 = ld_rlx(q0), v1 = ld_rlx(q1),
                               v2 = ld_rlx(q2), v3 = ld_rlx(q3);
            for (;;) {
                bool b0 = ((unsigned)v0 & TAGMASK) != tag;
                bool b1 = ((unsigned)v1 & TAGMASK) != tag;
                bool b2 = ((unsigned)v2 & TAGMASK) != tag;
                bool b3 = ((unsigned)v3 & TAGMASK) != tag;
                if (!(b0 | b1 | b2 | b3)) break;
                if (b0) v0 = ld_rlx(q0);
                if (b1) v1 = ld_rlx(q1);
                if (b2) v2 = ld_rlx(q2);
                if (b3) v3 = ld_rlx(q3);
            }
            __syncwarp();
            unsigned long long gm =
                warp_min64(umin64(umin64(v0, v1), umin64(v2, v3)));
            const unsigned bcell = ((unsigned)gm >> 14) & 0x3FFu;
            if (lane == 0) s_bmu[s & 1] = bcell;

            // 2) workers parked at bar1? (arrive-just-before-wait => safe)
            bar_wait(2);
            // 3) release workers for step s
            bar_arrive(1);

            // 4) publish step s+1 (operands from pass(s-1)/prologue, bar3)
            if (more) {
                bar_wait(3);  // satisfied long ago in steady state
                unsigned long long pk = 0xFFFFFFFFFFFFFFFFull;
                if (lane < SOM_CPC) {
                    float Pp = s_P[lane], Qp = s_Qm2[lane], Rp = s_R[lane];
                    float a = lut[(pgx - (int)(bcell >> 5) + 31) * 64 +
                                  (pgy - (int)(bcell & 31) + 31)];
                    float d2 = fmaxf(fmaf(a, fmaf(a, Rp, Qp), Pp), 0.0f);
                    pk = ((unsigned long long)__float_as_uint(d2) << 32)
                       | (pc << 14) | ((unsigned)(s + 2) & TAGMASK);
                }
                unsigned long long pm = warp_min64(pk);
                if (lane == 0) st_rlx(&g_slots[(s + 1) & 1][cta], pm);
            }
        }
    } else {
        // ================= WORKER WARPS (wid 0..7) =================
        bar_arrive(3);  // prologue P/Qm2/R are in smem

        for (int s = 0; s < S; s++) {
            // prefetch x_{s+2} (completion needed only inside the pass)
            float xf[SOM_EPW];
            {
                const float* xr =
                    X + (size_t)((s + 2) & (SOM_NS - 1)) * SOM_DIM + lane;
#pragma unroll
                for (int k = 0; k < SOM_EPW; k++) xf[k] = xr[k * 32];
            }

            bar_arrive(2);  // "parked" — immediately before the wait
            bar_wait(1);    // sleep until BMU(s)
            const unsigned bcell = s_bmu[s & 1];
            const float a = lut[(cgx - (int)(bcell >> 5) + 31) * 64 +
                                (cgy - (int)(bcell & 31) + 31)];

            float p = 0.f, q = 0.f, r = 0.f;
#pragma unroll
            for (int k = 0; k < SOM_EPW; k++) {
                float wn = fmaf(a, v[k], w[k]);   // w^(s+1)
                float u  = xn[k] - wn;            // next v
                float z  = xf[k] - wn;
                r = fmaf(u, u, r);
                q = fmaf(z, u, q);
                p = fmaf(z, z, p);
                w[k]  = wn;
                v[k]  = u;
                xn[k] = xf[k];
            }
#pragma unroll
            for (int o = 16; o; o >>= 1) {
                p += __shfl_xor_sync(0xffffffffu, p, o);
                q += __shfl_xor_sync(0xffffffffu, q, o);
                r += __shfl_xor_sync(0xffffffffu, r, o);
            }
            if (lane == 0) {
                s_P[wid]   = p;
                s_Qm2[wid] = -2.0f * q;
                s_R[wid]   = r;
            }
            bar_arrive(3);  // "data ready" for comm's publish of step s+2
        }

        // write final weights
        float* orow = out + (size_t)cell * SOM_DIM + lane;
#pragma unroll
        for (int k = 0; k < SOM_EPW; k++) orow[k * 32] = w[k];
    }
}

extern "C" void kernel_launch(void* const* d_in, const int* in_sizes, int n_in,
                              void* d_out, int out_size) {
    const float* X  = (const float*)d_in[0];
    const float* W0 = (const float*)d_in[1];
    const int* pep  = (const int*)d_in[3];
    (void)in_sizes; (void)n_in; (void)out_size;

    som_init_slots<<<1, 256>>>();
    som_kernel<<<SOM_G, SOM_TPB>>>(X, W0, pep, (float*)d_out);
}